// round 3
// baseline (speedup 1.0000x reference)
#include <cuda_runtime.h>
#include <math_constants.h>

#define NN 100000
#define NE 1000000
#define DD 64
#define ECAP 128

// ---- static scratch ----
__device__ __align__(16) float d_h[NN * DD];
__device__ __align__(16) float d_x[NN * DD];
__device__ float d_asrc[NN];
__device__ float d_adst[NN];
__device__ int   d_cnt[NN];
__device__ int   d_ell[NN * ECAP];   // 51.2 MB ELL adjacency (src per dst-slot)

#define FMA2(acc, a, b) \
    asm("fma.rn.f32x2 %0, %1, %2, %3;" : "=l"(acc) : "l"(a), "l"(b), "l"(acc))
#define PACKDUP(dst, v) \
    asm("mov.b64 %0, {%1, %1};" : "=l"(dst) : "f"(v))

union U64F2 { unsigned long long u; float f[2]; };

// ================= adjacency build (2 kernels, dst invariant across layers) ====

__global__ void zero_k() {
    int i = blockIdx.x * blockDim.x + threadIdx.x;
    if (i < NN) d_cnt[i] = 0;
}

__global__ void ell_k(const int* __restrict__ src, const int* __restrict__ dst) {
    int e = blockIdx.x * blockDim.x + threadIdx.x;
    if (e < NE) {
        int d = dst[e];
        int slot = atomicAdd(&d_cnt[d], 1);
        if (slot < ECAP) d_ell[d * ECAP + slot] = src[e];
    }
}

// ================= GEMM h = x @ W (FFMA2), fused attention logits ==============
// 128x64 tile, 128 threads, 8x8 per thread; x transposed in smem.

__global__ __launch_bounds__(128) void gemm_attn_k(
        const float* __restrict__ x_ext, int use_internal,
        const float* __restrict__ W,
        const float* __restrict__ att_s, const float* __restrict__ att_d)
{
    const float* __restrict__ x = use_internal ? d_x : x_ext;
    __shared__ __align__(16) float ws[64 * 64];
    __shared__ __align__(16) float xsT[64 * 128];
    int tid  = threadIdx.x;
    int row0 = blockIdx.x * 128;

    for (int i = tid; i < 1024; i += 128)
        ((float4*)ws)[i] = ((const float4*)W)[i];
    for (int i = tid; i < 2048; i += 128) {
        int r = i >> 4, c4 = i & 15;
        float4 v = make_float4(0.f, 0.f, 0.f, 0.f);
        int gr = row0 + r;
        if (gr < NN) v = ((const float4*)x)[gr * 16 + c4];
        int c = c4 * 4;
        xsT[(c + 0) * 128 + r] = v.x;
        xsT[(c + 1) * 128 + r] = v.y;
        xsT[(c + 2) * 128 + r] = v.z;
        xsT[(c + 3) * 128 + r] = v.w;
    }
    __syncthreads();

    int tx = (tid & 7) * 8;
    int ty = (tid >> 3) * 8;

    unsigned long long acc[8][4];
#pragma unroll
    for (int i = 0; i < 8; i++)
#pragma unroll
        for (int m = 0; m < 4; m++) acc[i][m] = 0ull;

#pragma unroll 4
    for (int k = 0; k < 64; k++) {
        float4 xa = *(const float4*)&xsT[k * 128 + ty];
        float4 xb = *(const float4*)&xsT[k * 128 + ty + 4];
        ulonglong2 wA = *(const ulonglong2*)&ws[k * 64 + tx];
        ulonglong2 wB = *(const ulonglong2*)&ws[k * 64 + tx + 4];
        float xv[8] = {xa.x, xa.y, xa.z, xa.w, xb.x, xb.y, xb.z, xb.w};
#pragma unroll
        for (int i = 0; i < 8; i++) {
            unsigned long long xp;
            PACKDUP(xp, xv[i]);
            FMA2(acc[i][0], xp, wA.x);
            FMA2(acc[i][1], xp, wA.y);
            FMA2(acc[i][2], xp, wB.x);
            FMA2(acc[i][3], xp, wB.y);
        }
    }

    float4 asA = *(const float4*)&att_s[tx];
    float4 asB = *(const float4*)&att_s[tx + 4];
    float4 adA = *(const float4*)&att_d[tx];
    float4 adB = *(const float4*)&att_d[tx + 4];

#pragma unroll
    for (int i = 0; i < 8; i++) {
        U64F2 u0, u1, u2, u3;
        u0.u = acc[i][0]; u1.u = acc[i][1]; u2.u = acc[i][2]; u3.u = acc[i][3];
        float o0 = u0.f[0], o1 = u0.f[1], o2 = u1.f[0], o3 = u1.f[1];
        float o4 = u2.f[0], o5 = u2.f[1], o6 = u3.f[0], o7 = u3.f[1];

        float ps = o0*asA.x + o1*asA.y + o2*asA.z + o3*asA.w
                 + o4*asB.x + o5*asB.y + o6*asB.z + o7*asB.w;
        float pd = o0*adA.x + o1*adA.y + o2*adA.z + o3*adA.w
                 + o4*adB.x + o5*adB.y + o6*adB.z + o7*adB.w;
#pragma unroll
        for (int off = 4; off; off >>= 1) {
            ps += __shfl_xor_sync(0xffffffffu, ps, off, 8);
            pd += __shfl_xor_sync(0xffffffffu, pd, off, 8);
        }
        int gr = row0 + ty + i;
        if (gr < NN) {
            *(float4*)&d_h[gr * 64 + tx]     = make_float4(o0, o1, o2, o3);
            *(float4*)&d_h[gr * 64 + tx + 4] = make_float4(o4, o5, o6, o7);
            if ((tid & 7) == 0) { d_asrc[gr] = ps; d_adst[gr] = pd; }
        }
    }
}

// ================= segment softmax + weighted gather (warp per node) ===========
// Edge srcs + softmax weights live in registers (one lane = one edge, deg<=32).
// Gather: 4 edges/iter, half-warps load float4 rows -> 2 LDG.128 in flight/lane.

__global__ __launch_bounds__(256) void aggregate_k(
        const float* __restrict__ bias, float* __restrict__ out_ext, int to_internal)
{
    float* __restrict__ out = to_internal ? d_x : out_ext;
    int w    = threadIdx.x >> 5;
    int lane = threadIdx.x & 31;
    int wid  = blockIdx.x * 8 + w;
    if (wid >= NN) return;

    int deg = d_cnt[wid];
    deg = deg > ECAP ? ECAP : deg;
    int half = lane >> 4, li = lane & 15;
    float4 b4 = ((const float4*)bias)[li];
    float4* op = (float4*)out + wid * 16 + li;

    if (deg == 0) { if (half == 0) *op = b4; return; }
    float adv = d_adst[wid];
    const int* row = d_ell + wid * ECAP;

    if (deg <= 32) {
        int s = (lane < deg) ? row[lane] : 0;
        float e = (lane < deg) ? (d_asrc[s] + adv) : -CUDART_INF_F;
        e = e > 0.f ? e : 0.2f * e;
        float mx = e;
#pragma unroll
        for (int off = 16; off; off >>= 1)
            mx = fmaxf(mx, __shfl_xor_sync(0xffffffffu, mx, off));
        float wt = __expf(e - mx);          // 0 for pad lanes
        float sm = wt;
#pragma unroll
        for (int off = 16; off; off >>= 1)
            sm += __shfl_xor_sync(0xffffffffu, sm, off);
        float inv = 1.f / (sm + 1e-16f);

        float4 acc = make_float4(0.f, 0.f, 0.f, 0.f);
        int iters = (deg + 3) >> 2;
        for (int it = 0; it < iters; it++) {
            int j0 = it * 4 + half;          // this half's first edge
            int   sA = __shfl_sync(0xffffffffu, s,  j0);
            float wA = __shfl_sync(0xffffffffu, wt, j0);
            int   sB = __shfl_sync(0xffffffffu, s,  j0 + 2);
            float wB = __shfl_sync(0xffffffffu, wt, j0 + 2);
            float4 hA = ((const float4*)(d_h + sA * 64))[li];
            float4 hB = ((const float4*)(d_h + sB * 64))[li];
            acc.x += wA * hA.x + wB * hB.x;
            acc.y += wA * hA.y + wB * hB.y;
            acc.z += wA * hA.z + wB * hB.z;
            acc.w += wA * hA.w + wB * hB.w;
        }
        acc.x += __shfl_xor_sync(0xffffffffu, acc.x, 16);
        acc.y += __shfl_xor_sync(0xffffffffu, acc.y, 16);
        acc.z += __shfl_xor_sync(0xffffffffu, acc.z, 16);
        acc.w += __shfl_xor_sync(0xffffffffu, acc.w, 16);
        if (half == 0) {
            float4 r;
            r.x = acc.x * inv + b4.x;
            r.y = acc.y * inv + b4.y;
            r.z = acc.z * inv + b4.z;
            r.w = acc.w * inv + b4.w;
            *op = r;
        }
    } else {
        // rare (deg in (32,128]) generic path
        float mx = -CUDART_INF_F;
        for (int j = lane; j < deg; j += 32) {
            float e = d_asrc[row[j]] + adv;
            e = e > 0.f ? e : 0.2f * e;
            mx = fmaxf(mx, e);
        }
#pragma unroll
        for (int off = 16; off; off >>= 1)
            mx = fmaxf(mx, __shfl_xor_sync(0xffffffffu, mx, off));
        float sm = 0.f;
        for (int j = lane; j < deg; j += 32) {
            float e = d_asrc[row[j]] + adv;
            e = e > 0.f ? e : 0.2f * e;
            sm += __expf(e - mx);
        }
#pragma unroll
        for (int off = 16; off; off >>= 1)
            sm += __shfl_xor_sync(0xffffffffu, sm, off);
        float inv = 1.f / (sm + 1e-16f);

        float4 acc = make_float4(0.f, 0.f, 0.f, 0.f);
        for (int j = half; j < deg; j += 2) {
            int s = row[j];
            float e = d_asrc[s] + adv;
            e = e > 0.f ? e : 0.2f * e;
            float wt = __expf(e - mx);
            float4 hv = ((const float4*)(d_h + s * 64))[li];
            acc.x += wt * hv.x; acc.y += wt * hv.y;
            acc.z += wt * hv.z; acc.w += wt * hv.w;
        }
        acc.x += __shfl_xor_sync(0xffffffffu, acc.x, 16);
        acc.y += __shfl_xor_sync(0xffffffffu, acc.y, 16);
        acc.z += __shfl_xor_sync(0xffffffffu, acc.z, 16);
        acc.w += __shfl_xor_sync(0xffffffffu, acc.w, 16);
        if (half == 0) {
            float4 r;
            r.x = acc.x * inv + b4.x;
            r.y = acc.y * inv + b4.y;
            r.z = acc.z * inv + b4.z;
            r.w = acc.w * inv + b4.w;
            *op = r;
        }
    }
}

// ================= launch =================

extern "C" void kernel_launch(void* const* d_in, const int* in_sizes, int n_in,
                              void* d_out, int out_size)
{
    const float* g     = (const float*)d_in[0];
    const int*   ei    = (const int*)  d_in[1];
    const float* W     = (const float*)d_in[2];
    const float* att_s = (const float*)d_in[3];
    const float* att_d = (const float*)d_in[4];
    const float* bias  = (const float*)d_in[5];
    float* out = (float*)d_out;

    const int* src = ei;
    const int* dst = ei + NE;

    zero_k<<<(NN + 255) / 256, 256>>>();
    ell_k<<<(NE + 255) / 256, 256>>>(src, dst);

    const int gemm_blocks = (NN + 127) / 128;   // 782
    const int agg_blocks  = (NN + 7) / 8;       // 12500

    for (int L = 0; L < 4; L++) {
        gemm_attn_k<<<gemm_blocks, 128>>>(L == 0 ? g : nullptr, L == 0 ? 0 : 1,
                                          W, att_s, att_d);
        aggregate_k<<<agg_blocks, 256>>>(bias, L == 3 ? out : nullptr,
                                         L == 3 ? 0 : 1);
    }
}

// round 4
// speedup vs baseline: 1.0785x; 1.0785x over previous
#include <cuda_runtime.h>
#include <math_constants.h>

#define NN 100000
#define NE 1000000
#define DD 64
#define ECAP 128

// ---- static scratch ----
__device__ __align__(16) float d_h[NN * DD];
__device__ __align__(16) float d_x[NN * DD];
__device__ float d_asrc[NN];
__device__ float d_adst[NN];
__device__ int   d_cnt[NN];
__device__ int   d_ell[NN * ECAP];

#define FMA2(acc, a, b) \
    asm("fma.rn.f32x2 %0, %1, %2, %3;" : "=l"(acc) : "l"(a), "l"(b), "l"(acc))
#define PACKDUP(dst, v) \
    asm("mov.b64 %0, {%1, %1};" : "=l"(dst) : "f"(v))

union U64F2 { unsigned long long u; float f[2]; };

// ================= adjacency build =================

__global__ void zero_k() {
    int i = blockIdx.x * blockDim.x + threadIdx.x;
    if (i < NN) d_cnt[i] = 0;
}

__global__ void ell_k(const int* __restrict__ src, const int* __restrict__ dst) {
    int e = blockIdx.x * blockDim.x + threadIdx.x;
    if (e < NE) {
        int d = dst[e];
        int slot = atomicAdd(&d_cnt[d], 1);
        if (slot < ECAP) d_ell[d * ECAP + slot] = src[e];
    }
}

// ================= GEMM h = x @ W (FFMA2), fused attention logits ==============
// 128x64 tile, 256 threads, 8 rows x 4 cols per thread.

__global__ __launch_bounds__(256) void gemm_attn_k(
        const float* __restrict__ x_ext, int use_internal,
        const float* __restrict__ W,
        const float* __restrict__ att_s, const float* __restrict__ att_d)
{
    const float* __restrict__ x = use_internal ? d_x : x_ext;
    __shared__ __align__(16) float ws[64 * 64];    // 16 KB
    __shared__ __align__(16) float xsT[64 * 128];  // 32 KB
    int tid  = threadIdx.x;
    int row0 = blockIdx.x * 128;

    for (int i = tid; i < 1024; i += 256)
        ((float4*)ws)[i] = ((const float4*)W)[i];
    for (int i = tid; i < 2048; i += 256) {
        int r = i >> 4, c4 = i & 15;
        float4 v = make_float4(0.f, 0.f, 0.f, 0.f);
        int gr = row0 + r;
        if (gr < NN) v = ((const float4*)x)[gr * 16 + c4];
        int c = c4 * 4;
        xsT[(c + 0) * 128 + r] = v.x;
        xsT[(c + 1) * 128 + r] = v.y;
        xsT[(c + 2) * 128 + r] = v.z;
        xsT[(c + 3) * 128 + r] = v.w;
    }
    __syncthreads();

    int tx = (tid & 15) * 4;         // 4 cols
    int ty = (tid >> 4) * 8;         // 8 rows

    unsigned long long acc[8][2];
#pragma unroll
    for (int i = 0; i < 8; i++) { acc[i][0] = 0ull; acc[i][1] = 0ull; }

#pragma unroll 8
    for (int k = 0; k < 64; k++) {
        float4 xa = *(const float4*)&xsT[k * 128 + ty];
        float4 xb = *(const float4*)&xsT[k * 128 + ty + 4];
        ulonglong2 wv = *(const ulonglong2*)&ws[k * 64 + tx];
        float xv[8] = {xa.x, xa.y, xa.z, xa.w, xb.x, xb.y, xb.z, xb.w};
#pragma unroll
        for (int i = 0; i < 8; i++) {
            unsigned long long xp;
            PACKDUP(xp, xv[i]);
            FMA2(acc[i][0], xp, wv.x);
            FMA2(acc[i][1], xp, wv.y);
        }
    }

    float4 as4 = ((const float4*)att_s)[tid & 15];
    float4 ad4 = ((const float4*)att_d)[tid & 15];

#pragma unroll
    for (int i = 0; i < 8; i++) {
        U64F2 u0, u1;
        u0.u = acc[i][0]; u1.u = acc[i][1];
        float o0 = u0.f[0], o1 = u0.f[1], o2 = u1.f[0], o3 = u1.f[1];

        float ps = o0*as4.x + o1*as4.y + o2*as4.z + o3*as4.w;
        float pd = o0*ad4.x + o1*ad4.y + o2*ad4.z + o3*ad4.w;
#pragma unroll
        for (int off = 8; off; off >>= 1) {
            ps += __shfl_xor_sync(0xffffffffu, ps, off, 16);
            pd += __shfl_xor_sync(0xffffffffu, pd, off, 16);
        }
        int gr = row0 + ty + i;
        if (gr < NN) {
            *(float4*)&d_h[gr * 64 + tx] = make_float4(o0, o1, o2, o3);
            if ((tid & 15) == 0) { d_asrc[gr] = ps; d_adst[gr] = pd; }
        }
    }
}

// ================= segment softmax + weighted gather (warp per node) ===========
// Logits phase pads smem with (clamped src, wt=0) -> gather loop is branch-free,
// 8 edges / iter, 4 independent LDG.128 per lane, FMA2 accumulate.

__global__ __launch_bounds__(256, 6) void aggregate_k(
        const float* __restrict__ bias, float* __restrict__ out_ext, int to_internal)
{
    __shared__ float2 sew[8][32];
    float* __restrict__ out = to_internal ? d_x : out_ext;
    int w    = threadIdx.x >> 5;
    int lane = threadIdx.x & 31;
    int wid  = blockIdx.x * 8 + w;
    if (wid >= NN) return;

    int deg = d_cnt[wid];
    deg = deg > ECAP ? ECAP : deg;
    int half = lane >> 4, li = lane & 15;
    float4 b4 = ((const float4*)bias)[li];
    float4* op = (float4*)out + wid * 16 + li;

    if (deg == 0) { if (half == 0) *op = b4; return; }
    float adv = d_adst[wid];
    const int* row = d_ell + wid * ECAP;

    if (deg <= 32) {
        int idx = lane < deg ? lane : deg - 1;
        int s = row[idx];
        float e = d_asrc[s] + adv;
        e = e > 0.f ? e : 0.2f * e;
        float mx = lane < deg ? e : -CUDART_INF_F;
#pragma unroll
        for (int off = 16; off; off >>= 1)
            mx = fmaxf(mx, __shfl_xor_sync(0xffffffffu, mx, off));
        float wt = lane < deg ? __expf(e - mx) : 0.f;
        float sm = wt;
#pragma unroll
        for (int off = 16; off; off >>= 1)
            sm += __shfl_xor_sync(0xffffffffu, sm, off);
        float inv = 1.f / (sm + 1e-16f);
        sew[w][lane] = make_float2(__int_as_float(s), wt);
        __syncwarp();

        unsigned long long a0 = 0ull, a1 = 0ull;
        int iters = (deg + 7) >> 3;
        for (int it = 0; it < iters; it++) {
            int base = it * 8 + half * 4;
            float2 p0 = sew[w][base + 0];
            float2 p1 = sew[w][base + 1];
            float2 p2 = sew[w][base + 2];
            float2 p3 = sew[w][base + 3];
            ulonglong2 h0 = ((const ulonglong2*)(d_h + __float_as_int(p0.x) * 64))[li];
            ulonglong2 h1 = ((const ulonglong2*)(d_h + __float_as_int(p1.x) * 64))[li];
            ulonglong2 h2 = ((const ulonglong2*)(d_h + __float_as_int(p2.x) * 64))[li];
            ulonglong2 h3 = ((const ulonglong2*)(d_h + __float_as_int(p3.x) * 64))[li];
            unsigned long long w0, w1, w2, w3;
            PACKDUP(w0, p0.y); PACKDUP(w1, p1.y);
            PACKDUP(w2, p2.y); PACKDUP(w3, p3.y);
            FMA2(a0, w0, h0.x); FMA2(a1, w0, h0.y);
            FMA2(a0, w1, h1.x); FMA2(a1, w1, h1.y);
            FMA2(a0, w2, h2.x); FMA2(a1, w2, h2.y);
            FMA2(a0, w3, h3.x); FMA2(a1, w3, h3.y);
        }
        U64F2 ua, ub;
        ua.u = a0; ub.u = a1;
        float f0 = ua.f[0], f1 = ua.f[1], f2 = ub.f[0], f3 = ub.f[1];
        f0 += __shfl_xor_sync(0xffffffffu, f0, 16);
        f1 += __shfl_xor_sync(0xffffffffu, f1, 16);
        f2 += __shfl_xor_sync(0xffffffffu, f2, 16);
        f3 += __shfl_xor_sync(0xffffffffu, f3, 16);
        if (half == 0) {
            float4 r;
            r.x = f0 * inv + b4.x;
            r.y = f1 * inv + b4.y;
            r.z = f2 * inv + b4.z;
            r.w = f3 * inv + b4.w;
            *op = r;
        }
    } else {
        // essentially-never path (Poisson(10) degree > 32)
        float mx = -CUDART_INF_F;
        for (int j = lane; j < deg; j += 32) {
            float e = d_asrc[row[j]] + adv;
            e = e > 0.f ? e : 0.2f * e;
            mx = fmaxf(mx, e);
        }
#pragma unroll
        for (int off = 16; off; off >>= 1)
            mx = fmaxf(mx, __shfl_xor_sync(0xffffffffu, mx, off));
        float sm = 0.f;
        for (int j = lane; j < deg; j += 32) {
            float e = d_asrc[row[j]] + adv;
            e = e > 0.f ? e : 0.2f * e;
            sm += __expf(e - mx);
        }
#pragma unroll
        for (int off = 16; off; off >>= 1)
            sm += __shfl_xor_sync(0xffffffffu, sm, off);
        float inv = 1.f / (sm + 1e-16f);

        float4 acc = make_float4(0.f, 0.f, 0.f, 0.f);
        for (int j = half; j < deg; j += 2) {
            int s = row[j];
            float e = d_asrc[s] + adv;
            e = e > 0.f ? e : 0.2f * e;
            float wt = __expf(e - mx);
            float4 hv = ((const float4*)(d_h + s * 64))[li];
            acc.x += wt * hv.x; acc.y += wt * hv.y;
            acc.z += wt * hv.z; acc.w += wt * hv.w;
        }
        acc.x += __shfl_xor_sync(0xffffffffu, acc.x, 16);
        acc.y += __shfl_xor_sync(0xffffffffu, acc.y, 16);
        acc.z += __shfl_xor_sync(0xffffffffu, acc.z, 16);
        acc.w += __shfl_xor_sync(0xffffffffu, acc.w, 16);
        if (half == 0) {
            float4 r;
            r.x = acc.x * inv + b4.x;
            r.y = acc.y * inv + b4.y;
            r.z = acc.z * inv + b4.z;
            r.w = acc.w * inv + b4.w;
            *op = r;
        }
    }
}

// ================= launch =================

extern "C" void kernel_launch(void* const* d_in, const int* in_sizes, int n_in,
                              void* d_out, int out_size)
{
    const float* g     = (const float*)d_in[0];
    const int*   ei    = (const int*)  d_in[1];
    const float* W     = (const float*)d_in[2];
    const float* att_s = (const float*)d_in[3];
    const float* att_d = (const float*)d_in[4];
    const float* bias  = (const float*)d_in[5];
    float* out = (float*)d_out;

    const int* src = ei;
    const int* dst = ei + NE;

    zero_k<<<(NN + 255) / 256, 256>>>();
    ell_k<<<(NE + 255) / 256, 256>>>(src, dst);

    const int gemm_blocks = (NN + 127) / 128;   // 782
    const int agg_blocks  = (NN + 7) / 8;       // 12500

    for (int L = 0; L < 4; L++) {
        gemm_attn_k<<<gemm_blocks, 256>>>(L == 0 ? g : nullptr, L == 0 ? 0 : 1,
                                          W, att_s, att_d);
        aggregate_k<<<agg_blocks, 256>>>(bias, L == 3 ? out : nullptr,
                                         L == 3 ? 0 : 1);
    }
}

// round 5
// speedup vs baseline: 1.1297x; 1.0475x over previous
#include <cuda_runtime.h>
#include <math_constants.h>

#define NN 100000
#define NE 1000000
#define DD 64
#define ECAP 128
#define XST 132   // padded transpose stride: conflict-light, 16B-aligned

// ---- static scratch ----
__device__ __align__(16) float d_h[NN * DD];
__device__ __align__(16) float d_x[NN * DD];
__device__ float d_asrc[NN];
__device__ float d_adst[NN];
__device__ int   d_cnt[NN];
__device__ int   d_ell[NN * ECAP];

#define FMA2(acc, a, b) \
    asm("fma.rn.f32x2 %0, %1, %2, %3;" : "=l"(acc) : "l"(a), "l"(b), "l"(acc))
#define PACKDUP(dst, v) \
    asm("mov.b64 %0, {%1, %1};" : "=l"(dst) : "f"(v))

union U64F2 { unsigned long long u; float f[2]; };

// ================= adjacency build =================

__global__ void zero_k() {
    int i = blockIdx.x * blockDim.x + threadIdx.x;
    if (i < NN) d_cnt[i] = 0;
}

__global__ void ell_k(const int* __restrict__ src, const int* __restrict__ dst) {
    int e = blockIdx.x * blockDim.x + threadIdx.x;
    if (e < NE) {
        int d = dst[e];
        int slot = atomicAdd(&d_cnt[d], 1);
        if (slot < ECAP) d_ell[d * ECAP + slot] = src[e];
    }
}

// ================= GEMM h = x @ W (FFMA2), fused attention logits ==============
// 128x64 tile, 256 threads, 8 rows x 4 cols per thread. xsT stride 132.

__global__ __launch_bounds__(256) void gemm_attn_k(
        const float* __restrict__ x_ext, int use_internal,
        const float* __restrict__ W,
        const float* __restrict__ att_s, const float* __restrict__ att_d)
{
    const float* __restrict__ x = use_internal ? d_x : x_ext;
    __shared__ __align__(16) float ws[64 * 64];     // 16 KB
    __shared__ __align__(16) float xsT[64 * XST];   // 33.8 KB
    int tid  = threadIdx.x;
    int row0 = blockIdx.x * 128;

    for (int i = tid; i < 1024; i += 256)
        ((float4*)ws)[i] = ((const float4*)W)[i];
    for (int i = tid; i < 2048; i += 256) {
        int r = i >> 4, c4 = i & 15;
        float4 v = make_float4(0.f, 0.f, 0.f, 0.f);
        int gr = row0 + r;
        if (gr < NN) v = ((const float4*)x)[gr * 16 + c4];
        int c = c4 * 4;
        xsT[(c + 0) * XST + r] = v.x;
        xsT[(c + 1) * XST + r] = v.y;
        xsT[(c + 2) * XST + r] = v.z;
        xsT[(c + 3) * XST + r] = v.w;
    }
    __syncthreads();

    int tx = (tid & 15) * 4;
    int ty = (tid >> 4) * 8;

    unsigned long long acc[8][2];
#pragma unroll
    for (int i = 0; i < 8; i++) { acc[i][0] = 0ull; acc[i][1] = 0ull; }

#pragma unroll 8
    for (int k = 0; k < 64; k++) {
        float4 xa = *(const float4*)&xsT[k * XST + ty];
        float4 xb = *(const float4*)&xsT[k * XST + ty + 4];
        ulonglong2 wv = *(const ulonglong2*)&ws[k * 64 + tx];
        float xv[8] = {xa.x, xa.y, xa.z, xa.w, xb.x, xb.y, xb.z, xb.w};
#pragma unroll
        for (int i = 0; i < 8; i++) {
            unsigned long long xp;
            PACKDUP(xp, xv[i]);
            FMA2(acc[i][0], xp, wv.x);
            FMA2(acc[i][1], xp, wv.y);
        }
    }

    float4 as4 = ((const float4*)att_s)[tid & 15];
    float4 ad4 = ((const float4*)att_d)[tid & 15];

#pragma unroll
    for (int i = 0; i < 8; i++) {
        U64F2 u0, u1;
        u0.u = acc[i][0]; u1.u = acc[i][1];
        float o0 = u0.f[0], o1 = u0.f[1], o2 = u1.f[0], o3 = u1.f[1];

        float ps = o0*as4.x + o1*as4.y + o2*as4.z + o3*as4.w;
        float pd = o0*ad4.x + o1*ad4.y + o2*ad4.z + o3*ad4.w;
#pragma unroll
        for (int off = 8; off; off >>= 1) {
            ps += __shfl_xor_sync(0xffffffffu, ps, off, 16);
            pd += __shfl_xor_sync(0xffffffffu, pd, off, 16);
        }
        int gr = row0 + ty + i;
        if (gr < NN) {
            *(float4*)&d_h[gr * 64 + tx] = make_float4(o0, o1, o2, o3);
            if ((tid & 15) == 0) { d_asrc[gr] = ps; d_adst[gr] = pd; }
        }
    }
}

// ================= segment softmax + weighted gather (warp per node) ===========
// Denominator accumulated DURING the gather; only one shfl-reduce (max) before it.
// 8 blocks/SM (reg cap 32) for latency hiding.

__global__ __launch_bounds__(256, 8) void aggregate_k(
        const float* __restrict__ bias, float* __restrict__ out_ext, int to_internal)
{
    __shared__ float2 sew[8][32];
    float* __restrict__ out = to_internal ? d_x : out_ext;
    int w    = threadIdx.x >> 5;
    int lane = threadIdx.x & 31;
    int wid  = blockIdx.x * 8 + w;
    if (wid >= NN) return;

    int deg = d_cnt[wid];
    deg = deg > ECAP ? ECAP : deg;
    int half = lane >> 4, li = lane & 15;
    float4 b4 = ((const float4*)bias)[li];
    float4* op = (float4*)out + wid * 16 + li;

    if (deg == 0) { if (half == 0) *op = b4; return; }
    float adv = d_adst[wid];
    const int* row = d_ell + wid * ECAP;

    if (deg <= 32) {
        int idx = lane < deg ? lane : deg - 1;
        int s = row[idx];
        float e = d_asrc[s] + adv;
        e = e > 0.f ? e : 0.2f * e;
        float mx = lane < deg ? e : -CUDART_INF_F;
#pragma unroll
        for (int off = 16; off; off >>= 1)
            mx = fmaxf(mx, __shfl_xor_sync(0xffffffffu, mx, off));
        float wt = lane < deg ? __expf(e - mx) : 0.f;
        sew[w][lane] = make_float2(__int_as_float(s), wt);
        __syncwarp();

        unsigned long long a0 = 0ull, a1 = 0ull;
        float den = 0.f;
        int iters = (deg + 7) >> 3;
        for (int it = 0; it < iters; it++) {
            int base = it * 8 + half * 4;
            float2 p0 = sew[w][base + 0];
            float2 p1 = sew[w][base + 1];
            float2 p2 = sew[w][base + 2];
            float2 p3 = sew[w][base + 3];
            ulonglong2 h0 = ((const ulonglong2*)(d_h + __float_as_int(p0.x) * 64))[li];
            ulonglong2 h1 = ((const ulonglong2*)(d_h + __float_as_int(p1.x) * 64))[li];
            ulonglong2 h2 = ((const ulonglong2*)(d_h + __float_as_int(p2.x) * 64))[li];
            ulonglong2 h3 = ((const ulonglong2*)(d_h + __float_as_int(p3.x) * 64))[li];
            den += (p0.y + p1.y) + (p2.y + p3.y);
            unsigned long long w0, w1, w2, w3;
            PACKDUP(w0, p0.y); PACKDUP(w1, p1.y);
            PACKDUP(w2, p2.y); PACKDUP(w3, p3.y);
            FMA2(a0, w0, h0.x); FMA2(a1, w0, h0.y);
            FMA2(a0, w1, h1.x); FMA2(a1, w1, h1.y);
            FMA2(a0, w2, h2.x); FMA2(a1, w2, h2.y);
            FMA2(a0, w3, h3.x); FMA2(a1, w3, h3.y);
        }
        U64F2 ua, ub;
        ua.u = a0; ub.u = a1;
        float f0 = ua.f[0], f1 = ua.f[1], f2 = ub.f[0], f3 = ub.f[1];
        f0  += __shfl_xor_sync(0xffffffffu, f0, 16);
        f1  += __shfl_xor_sync(0xffffffffu, f1, 16);
        f2  += __shfl_xor_sync(0xffffffffu, f2, 16);
        f3  += __shfl_xor_sync(0xffffffffu, f3, 16);
        den += __shfl_xor_sync(0xffffffffu, den, 16);
        if (half == 0) {
            float inv = 1.f / (den + 1e-16f);
            float4 r;
            r.x = f0 * inv + b4.x;
            r.y = f1 * inv + b4.y;
            r.z = f2 * inv + b4.z;
            r.w = f3 * inv + b4.w;
            *op = r;
        }
    } else {
        // essentially-never path (Poisson(10) degree > 32)
        float mx = -CUDART_INF_F;
        for (int j = lane; j < deg; j += 32) {
            float e = d_asrc[row[j]] + adv;
            e = e > 0.f ? e : 0.2f * e;
            mx = fmaxf(mx, e);
        }
#pragma unroll
        for (int off = 16; off; off >>= 1)
            mx = fmaxf(mx, __shfl_xor_sync(0xffffffffu, mx, off));
        float sm = 0.f;
        for (int j = lane; j < deg; j += 32) {
            float e = d_asrc[row[j]] + adv;
            e = e > 0.f ? e : 0.2f * e;
            sm += __expf(e - mx);
        }
#pragma unroll
        for (int off = 16; off; off >>= 1)
            sm += __shfl_xor_sync(0xffffffffu, sm, off);
        float inv = 1.f / (sm + 1e-16f);

        float4 acc = make_float4(0.f, 0.f, 0.f, 0.f);
        for (int j = half; j < deg; j += 2) {
            int s = row[j];
            float e = d_asrc[s] + adv;
            e = e > 0.f ? e : 0.2f * e;
            float wt = __expf(e - mx);
            float4 hv = ((const float4*)(d_h + s * 64))[li];
            acc.x += wt * hv.x; acc.y += wt * hv.y;
            acc.z += wt * hv.z; acc.w += wt * hv.w;
        }
        acc.x += __shfl_xor_sync(0xffffffffu, acc.x, 16);
        acc.y += __shfl_xor_sync(0xffffffffu, acc.y, 16);
        acc.z += __shfl_xor_sync(0xffffffffu, acc.z, 16);
        acc.w += __shfl_xor_sync(0xffffffffu, acc.w, 16);
        if (half == 0) {
            float4 r;
            r.x = acc.x * inv + b4.x;
            r.y = acc.y * inv + b4.y;
            r.z = acc.z * inv + b4.z;
            r.w = acc.w * inv + b4.w;
            *op = r;
        }
    }
}

// ================= launch =================

extern "C" void kernel_launch(void* const* d_in, const int* in_sizes, int n_in,
                              void* d_out, int out_size)
{
    const float* g     = (const float*)d_in[0];
    const int*   ei    = (const int*)  d_in[1];
    const float* W     = (const float*)d_in[2];
    const float* att_s = (const float*)d_in[3];
    const float* att_d = (const float*)d_in[4];
    const float* bias  = (const float*)d_in[5];
    float* out = (float*)d_out;

    const int* src = ei;
    const int* dst = ei + NE;

    zero_k<<<(NN + 255) / 256, 256>>>();
    ell_k<<<(NE + 255) / 256, 256>>>(src, dst);

    const int gemm_blocks = (NN + 127) / 128;   // 782
    const int agg_blocks  = (NN + 7) / 8;       // 12500

    for (int L = 0; L < 4; L++) {
        gemm_attn_k<<<gemm_blocks, 256>>>(L == 0 ? g : nullptr, L == 0 ? 0 : 1,
                                          W, att_s, att_d);
        aggregate_k<<<agg_blocks, 256>>>(bias, L == 3 ? out : nullptr,
                                         L == 3 ? 0 : 1);
    }
}